// round 14
// baseline (speedup 1.0000x reference)
#include <cuda_runtime.h>
#include <math.h>

// ---------------------------------------------------------------------------
// OwlViT prediction head
//   B=32, P=576, DV=768, DT=512, N_PARTS=12, K=3, NUM_CLASSES=800
//   out = [logits_reshaped (384*9600) | pred_logits (32*800)] fp32
// ---------------------------------------------------------------------------

#define Bsz 32
#define Pn 576
#define DV 768
#define DT 512
#define NPART 12
#define TOPK 3
#define NCLS 800
#define NQ (NCLS * NPART)      // 9600 query rows per batch
#define MROWS (Bsz * NPART)    // 384
#define LOGITS_ELEMS ((size_t)MROWS * NQ)

// scratch (static device memory; no allocations allowed)
__device__ float g_h1[MROWS * DV];
__device__ float g_h2[MROWS * DV];
__device__ float g_img[MROWS * DT];

// ---------------------------------------------------------------------------
__device__ __forceinline__ void fma2(unsigned long long& d,
                                     unsigned long long a,
                                     unsigned long long b) {
    asm("fma.rn.f32x2 %0, %1, %2, %0;" : "+l"(d) : "l"(a), "l"(b));
}

__device__ __forceinline__ float pair_sum(unsigned long long v) {
    float lo = __uint_as_float((unsigned)(v & 0xffffffffull));
    float hi = __uint_as_float((unsigned)(v >> 32));
    return lo + hi;
}

__device__ __forceinline__ float gelu_exact(float x) {
    return 0.5f * x * (1.0f + erff(x * 0.70710678118654752f));
}

__device__ __forceinline__ void cp_async16(unsigned dst, const void* src) {
    asm volatile("cp.async.cg.shared.global [%0], [%1], 16;"
                 :: "r"(dst), "l"(src));
}
__device__ __forceinline__ void cp_commit() {
    asm volatile("cp.async.commit_group;");
}
__device__ __forceinline__ void cp_wait2() {
    asm volatile("cp.async.wait_group 2;");
}
__device__ __forceinline__ void cp_wait1() {
    asm volatile("cp.async.wait_group 1;");
}
__device__ __forceinline__ void cp_wait0() {
    asm volatile("cp.async.wait_group 0;");
}

// ---------------------------------------------------------------------------
// GEMM: C[M,N] = gelu(A[M,768] * W[N,768]^T + bias), smem double-buffered.
// BM=32 BN=64 BK=32, 256 threads, 2x4 outputs/thread, f32x2 k-pair FMAs.
// GATHER=true: A row r is the dedup-sum of topk image rows (fused gather).
// ---------------------------------------------------------------------------
#define GBM 32
#define GBN 64
#define GBK 32
#define GPAD 36
#define NITER (DV / GBK)   // 24

template<bool GATHER>
__global__ void __launch_bounds__(256)
gemm_kernel(const float* __restrict__ A, const float* __restrict__ W,
            const float* __restrict__ bias, float* __restrict__ C, int N,
            const int* __restrict__ idx) {
    __shared__ __align__(16) float As[2][GBM][GPAD];
    __shared__ __align__(16) float Ws[2][GBN][GPAD];
    int t = threadIdx.x;
    int tx = t & 15;                 // cols tx + 16j
    int ty = t >> 4;                 // rows ty*2 + i
    int bm = blockIdx.x * GBM, bn = blockIdx.y * GBN;

    int ar = t >> 3, ak = (t & 7) * 4;    // A tile: 1 float4/thread
    int wr = t >> 2, wk = (t & 3) * 8;    // W tile: 2 float4/thread

    const float *Arow0, *Arow1, *Arow2;
    bool u1 = false, u2 = false;
    if (GATHER) {
        int row = bm + ar;
        int bb = row / NPART, n = row - bb * NPART;
        int i0 = idx[(bb * TOPK + 0) * NPART + n];
        int i1 = idx[(bb * TOPK + 1) * NPART + n];
        int i2 = idx[(bb * TOPK + 2) * NPART + n];
        i0 = min(max(i0, 0), Pn - 1);
        i1 = min(max(i1, 0), Pn - 1);
        i2 = min(max(i2, 0), Pn - 1);
        u1 = (i1 != i0);
        u2 = (i2 != i0) && (i2 != i1);
        const float* base = A + (size_t)bb * Pn * DV;
        Arow0 = base + (size_t)i0 * DV;
        Arow1 = base + (size_t)i1 * DV;
        Arow2 = base + (size_t)i2 * DV;
    } else {
        Arow0 = A + (size_t)(bm + ar) * DV;
        Arow1 = Arow0; Arow2 = Arow0;
    }
    const float* Wg = W + (size_t)(bn + wr) * DV;

    auto loadA = [&](int k0) -> float4 {
        float4 s = *(const float4*)(Arow0 + k0 + ak);
        if (GATHER) {
            if (u1) { float4 v = *(const float4*)(Arow1 + k0 + ak);
                      s.x += v.x; s.y += v.y; s.z += v.z; s.w += v.w; }
            if (u2) { float4 v = *(const float4*)(Arow2 + k0 + ak);
                      s.x += v.x; s.y += v.y; s.z += v.z; s.w += v.w; }
        }
        return s;
    };

    unsigned long long acc2[2][4];
#pragma unroll
    for (int i = 0; i < 2; ++i)
#pragma unroll
        for (int j = 0; j < 4; ++j) acc2[i][j] = 0ull;

    // prologue: tile0 -> smem[0]; tile1 -> regs
    float4 a_r = loadA(0);
    float4 w_r0 = *(const float4*)(Wg + wk);
    float4 w_r1 = *(const float4*)(Wg + wk + 4);
    *(float4*)&As[0][ar][ak] = a_r;
    *(float4*)&Ws[0][wr][wk] = w_r0;
    *(float4*)&Ws[0][wr][wk + 4] = w_r1;
    a_r  = loadA(GBK);
    w_r0 = *(const float4*)(Wg + GBK + wk);
    w_r1 = *(const float4*)(Wg + GBK + wk + 4);
    __syncthreads();

#pragma unroll 1
    for (int i = 0; i < NITER; ++i) {
        int buf = i & 1, nbuf = buf ^ 1;
        if (i + 1 < NITER) {
            *(float4*)&As[nbuf][ar][ak] = a_r;
            *(float4*)&Ws[nbuf][wr][wk] = w_r0;
            *(float4*)&Ws[nbuf][wr][wk + 4] = w_r1;
        }
        if (i + 2 < NITER) {
            int k0 = (i + 2) * GBK;
            a_r  = loadA(k0);
            w_r0 = *(const float4*)(Wg + k0 + wk);
            w_r1 = *(const float4*)(Wg + k0 + wk + 4);
        }
#pragma unroll
        for (int kk = 0; kk < GBK; kk += 4) {
            ulonglong2 ap[2], wp[4];
            ap[0] = *(const ulonglong2*)&As[buf][ty * 2][kk];
            ap[1] = *(const ulonglong2*)&As[buf][ty * 2 + 1][kk];
#pragma unroll
            for (int j = 0; j < 4; ++j)
                wp[j] = *(const ulonglong2*)&Ws[buf][tx + 16 * j][kk];
#pragma unroll
            for (int ii = 0; ii < 2; ++ii)
#pragma unroll
                for (int j = 0; j < 4; ++j) {
                    fma2(acc2[ii][j], ap[ii].x, wp[j].x);
                    fma2(acc2[ii][j], ap[ii].y, wp[j].y);
                }
        }
        __syncthreads();
    }

#pragma unroll
    for (int i = 0; i < 2; ++i) {
        int row = bm + ty * 2 + i;
#pragma unroll
        for (int j = 0; j < 4; ++j) {
            int col = bn + tx + 16 * j;
            float x = pair_sum(acc2[i][j]) + bias[col];
            C[(size_t)row * N + col] = gelu_exact(x);
        }
    }
}

// ---------------------------------------------------------------------------
// logits: lane-owns-row, 2 rows/thread, cp.async 4-stage pipeline.
// Block = 128 threads owning rows {t, t+128} of a 256-row stripe.
// q tiles 256 rows x 8 k (8KB), 4 buffers -> 3 groups in flight; the wait
// for group t fires 3 tile-periods after issue (R12's S=3 exposed loaded
// DRAM latency every tile: all pipes idled at ~35%).
// Issue for tile t+3 happens right AFTER the barrier of tile t (safe: it
// targets buf (t-1)%4 whose readers all passed that barrier).
// Tail: pending = min(3, NT - tile) at loop top -> wait2 / wait1 / wait0.
// q LDS indices are tile-invariant (hoisted); img addressed by one pointer
// advanced +32B/tile (immediate-offset LDS) to cut ALU.
// Dynamic smem: q 4x8KB + img 24KB = 56KB -> 4 blocks/SM.
// ---------------------------------------------------------------------------
#define QT 8
#define NT (DT / QT)     // 64 tiles
#define RPT 2
#define TPB 128
#define RPB 256          // grid.x = ceil(9600/256) = 38 (last block guarded)
#define QBUF (RPB * 2)   // float4s per buffer (2 slots x 256 rows) = 8KB

__global__ void __launch_bounds__(TPB, 4)
logits_kernel(const float* __restrict__ q, float* __restrict__ out) {
    extern __shared__ __align__(16) float smem[];
    float4* q_s  = (float4*)smem;          // [4][2][256] float4 = 32KB
    float* img_s = smem + 8192;            // 12*512 floats = 24KB

    int t = threadIdx.x;
    int warp = t >> 5, lane = t & 31;
    int b = blockIdx.y;
    int r0 = blockIdx.x * RPB;

    const float* qB = q + (size_t)b * NQ * DT;

    // --- staging setup: 4 float4/thread/tile ---
    // idx = j*128 + t -> row = idx>>1 (2 lanes per row), slot = idx&1.
    // Persistent source pointers, advanced +QT floats per issued tile.
    const float* srcp[4];
    unsigned dst0[4];                      // dst smem addr for buf 0
#pragma unroll
    for (int j = 0; j < 4; ++j) {
        int idx = j * TPB + t;
        int row = idx >> 1, slot = idx & 1;
        int rg = r0 + row; if (rg > NQ - 1) rg = NQ - 1;   // last-block clamp
        srcp[j] = qB + (size_t)rg * DT + slot * 4;
        int rr = (row + 4 * slot) & (RPB - 1);             // rotation: slot1 +4
        dst0[j] = (unsigned)__cvta_generic_to_shared(
            &q_s[slot * RPB + rr]);
    }

    auto issueTile = [&](int buf) {
        unsigned boff = (unsigned)buf * (QBUF * 16);       // bytes per buffer
#pragma unroll
        for (int j = 0; j < 4; ++j) {
            cp_async16(dst0[j] + boff, srcp[j]);
            srcp[j] += QT;
        }
        cp_commit();
    };

    // prologue: 3 groups in flight before first compute
    issueTile(0);
    issueTile(1);
    issueTile(2);

    {   // stage img tile for this batch (1536 float4, 12/thread)
        const float4* src = (const float4*)(g_img + (size_t)b * NPART * DT);
        float4* dst = (float4*)img_s;
#pragma unroll
        for (int i = 0; i < 12; ++i)
            dst[t + i * TPB] = src[t + i * TPB];
    }
    __syncthreads();

    // fused l2 normalization of the 12 img rows (4 warps, 3 rows each)
    for (int row = warp; row < NPART; row += 4) {
        float* rp = img_s + row * DT;
        float4 v0 = *(float4*)(rp + lane * 4);
        float4 v1 = *(float4*)(rp + lane * 4 + 128);
        float4 v2 = *(float4*)(rp + lane * 4 + 256);
        float4 v3 = *(float4*)(rp + lane * 4 + 384);
        float ss = v0.x*v0.x + v0.y*v0.y + v0.z*v0.z + v0.w*v0.w
                 + v1.x*v1.x + v1.y*v1.y + v1.z*v1.z + v1.w*v1.w
                 + v2.x*v2.x + v2.y*v2.y + v2.z*v2.z + v2.w*v2.w
                 + v3.x*v3.x + v3.y*v3.y + v3.z*v3.z + v3.w*v3.w;
#pragma unroll
        for (int off = 16; off > 0; off >>= 1)
            ss += __shfl_xor_sync(0xffffffffu, ss, off);
        float rinv = 1.0f / fmaxf(sqrtf(ss), 1e-12f);
        v0.x*=rinv; v0.y*=rinv; v0.z*=rinv; v0.w*=rinv;
        v1.x*=rinv; v1.y*=rinv; v1.z*=rinv; v1.w*=rinv;
        v2.x*=rinv; v2.y*=rinv; v2.z*=rinv; v2.w*=rinv;
        v3.x*=rinv; v3.y*=rinv; v3.z*=rinv; v3.w*=rinv;
        *(float4*)(rp + lane * 4)       = v0;
        *(float4*)(rp + lane * 4 + 128) = v1;
        *(float4*)(rp + lane * 4 + 256) = v2;
        *(float4*)(rp + lane * 4 + 384) = v3;
    }
    // img-norm visibility to all warps is covered by the first in-loop
    // __syncthreads below (before any compute reads img_s).

    // hoisted, tile-invariant q LDS indices: [r][c] -> c*RPB + rr
    int qidx[RPT][2];
#pragma unroll
    for (int r = 0; r < RPT; ++r)
#pragma unroll
        for (int c = 0; c < 2; ++c)
            qidx[r][c] = c * RPB + ((t + TPB * r + 4 * c) & (RPB - 1));

    unsigned long long acc[RPT][13];
#pragma unroll
    for (int r = 0; r < RPT; ++r)
#pragma unroll
        for (int j = 0; j < 13; ++j) acc[r][j] = 0ull;

    int boff = 0;                          // float4 offset of current buffer
    const float* ik = img_s;               // advanced +QT floats per tile
#pragma unroll 1
    for (int tile = 0; tile < NT; ++tile) {
        // pending groups at loop top = min(3, NT - tile):
        //   tile <  NT-2 -> 3 pending, drain oldest  -> wait_group(2)
        //   tile == NT-2 -> 2 pending                -> wait_group(1)
        //   tile == NT-1 -> 1 pending, drain all     -> wait_group(0)
        if (tile < NT - 2) cp_wait2();
        else if (tile == NT - 2) cp_wait1();
        else cp_wait0();
        __syncthreads();             // all threads' copies + img norm visible

        // issue tile+3 into buf (tile+3)&3 == (tile-1)&3: its readers all
        // passed the barrier above.
        if (tile + 3 < NT) issueTile((tile + 3) & 3);

        const float4* qbuf = q_s + boff;
#pragma unroll
        for (int c = 0; c < 2; ++c) {
            ulonglong2 qp[RPT];
#pragma unroll
            for (int r = 0; r < RPT; ++r)
                qp[r] = *(const ulonglong2*)&qbuf[qidx[r][c]];
#pragma unroll
            for (int n = 0; n < NPART; ++n) {
                ulonglong2 im = *(const ulonglong2*)&ik[n * DT + c * 4];
#pragma unroll
                for (int r = 0; r < RPT; ++r) {
                    fma2(acc[r][n], qp[r].x, im.x);
                    fma2(acc[r][n], qp[r].y, im.y);
                }
            }
#pragma unroll
            for (int r = 0; r < RPT; ++r) {
                fma2(acc[r][12], qp[r].x, qp[r].x);
                fma2(acc[r][12], qp[r].y, qp[r].y);
            }
        }
        ik += QT;
        boff += QBUF; if (boff == 4 * QBUF) boff = 0;
    }

#pragma unroll
    for (int r = 0; r < RPT; ++r) {
        int gr = r0 + t + TPB * r;
        if (gr >= NQ) break;                  // last-block guard
        float s[13];
#pragma unroll
        for (int j = 0; j < 13; ++j) s[j] = pair_sum(acc[r][j]);
        float rinv = 1.0f / fmaxf(sqrtf(s[12]), 1e-12f);
#pragma unroll
        for (int n = 0; n < NPART; ++n)
            out[((size_t)(b * NPART + n)) * NQ + gr] = s[n] * rinv;
    }
}

// ---------------------------------------------------------------------------
// pred_logits[b,c] = sum_n logits[b,n,c*12+n]
// ---------------------------------------------------------------------------
__global__ void pred_kernel(float* __restrict__ out) {
    int t = blockIdx.x * blockDim.x + threadIdx.x;   // 0..25599
    if (t >= Bsz * NCLS) return;
    int b = t / NCLS, c = t % NCLS;
    float s = 0.0f;
#pragma unroll
    for (int n = 0; n < NPART; ++n)
        s += out[((size_t)(b * NPART + n)) * NQ + c * NPART + n];
    out[LOGITS_ELEMS + t] = s;
}

// ---------------------------------------------------------------------------
extern "C" void kernel_launch(void* const* d_in, const int* in_sizes, int n_in,
                              void* d_out, int out_size) {
    const float* image = (const float*)d_in[0];
    const float* query = (const float*)d_in[1];
    const int* topk = (const int*)d_in[2];
    const float* W1 = (const float*)d_in[3];
    const float* b1 = (const float*)d_in[4];
    const float* W2 = (const float*)d_in[5];
    const float* b2 = (const float*)d_in[6];
    const float* W3 = (const float*)d_in[7];
    const float* b3 = (const float*)d_in[8];
    float* out = (float*)d_out;

    float* h1; float* h2; float* img;
    cudaGetSymbolAddress((void**)&h1, g_h1);
    cudaGetSymbolAddress((void**)&h2, g_h2);
    cudaGetSymbolAddress((void**)&img, g_img);

    const int LOGITS_SMEM = 57344;   // 32KB q (4 buf) + 24KB img
    cudaFuncSetAttribute(logits_kernel,
                         cudaFuncAttributeMaxDynamicSharedMemorySize,
                         LOGITS_SMEM);

    // launch order keeps logits at global index 5 (2 harness preamble
    // launches + 3 here) so ncu -s 5 -c 1 captures it.
    gemm_kernel<true ><<<dim3(MROWS / GBM, DV / GBN), 256>>>(image, W1, b1, h1, DV, topk);
    gemm_kernel<false><<<dim3(MROWS / GBM, DV / GBN), 256>>>(h1, W2, b2, h2, DV, nullptr);
    gemm_kernel<false><<<dim3(MROWS / GBM, DT / GBN), 256>>>(h2, W3, b3, img, DT, nullptr);
    logits_kernel<<<dim3((NQ + RPB - 1) / RPB, Bsz), TPB, LOGITS_SMEM>>>(query, out);
    pred_kernel<<<(Bsz * NCLS + 255) / 256, 256>>>(out);
}

// round 15
// speedup vs baseline: 1.0547x; 1.0547x over previous
#include <cuda_runtime.h>
#include <math.h>

// ---------------------------------------------------------------------------
// OwlViT prediction head
//   B=32, P=576, DV=768, DT=512, N_PARTS=12, K=3, NUM_CLASSES=800
//   out = [logits_reshaped (384*9600) | pred_logits (32*800)] fp32
// ---------------------------------------------------------------------------

#define Bsz 32
#define Pn 576
#define DV 768
#define DT 512
#define NPART 12
#define TOPK 3
#define NCLS 800
#define NQ (NCLS * NPART)      // 9600 query rows per batch
#define MROWS (Bsz * NPART)    // 384
#define LOGITS_ELEMS ((size_t)MROWS * NQ)

// scratch (static device memory; no allocations allowed)
__device__ float g_h1[MROWS * DV];
__device__ float g_h2[MROWS * DV];
__device__ float g_img[MROWS * DT];

// ---------------------------------------------------------------------------
__device__ __forceinline__ void fma2(unsigned long long& d,
                                     unsigned long long a,
                                     unsigned long long b) {
    asm("fma.rn.f32x2 %0, %1, %2, %0;" : "+l"(d) : "l"(a), "l"(b));
}

__device__ __forceinline__ float pair_sum(unsigned long long v) {
    float lo = __uint_as_float((unsigned)(v & 0xffffffffull));
    float hi = __uint_as_float((unsigned)(v >> 32));
    return lo + hi;
}

__device__ __forceinline__ float gelu_exact(float x) {
    return 0.5f * x * (1.0f + erff(x * 0.70710678118654752f));
}

__device__ __forceinline__ void cp_async16(unsigned dst, const void* src) {
    asm volatile("cp.async.cg.shared.global [%0], [%1], 16;"
                 :: "r"(dst), "l"(src));
}
__device__ __forceinline__ void cp_commit() {
    asm volatile("cp.async.commit_group;");
}
__device__ __forceinline__ void cp_wait2() {
    asm volatile("cp.async.wait_group 2;");
}
__device__ __forceinline__ void cp_wait1() {
    asm volatile("cp.async.wait_group 1;");
}
__device__ __forceinline__ void cp_wait0() {
    asm volatile("cp.async.wait_group 0;");
}

// ---------------------------------------------------------------------------
// GEMM: C[M,N] = gelu(A[M,768] * W[N,768]^T + bias), smem double-buffered.
// BM=32 BN=64 BK=32, 256 threads, 2x4 outputs/thread, f32x2 k-pair FMAs.
// GATHER=true: A row r is the dedup-sum of topk image rows (fused gather).
// ---------------------------------------------------------------------------
#define GBM 32
#define GBN 64
#define GBK 32
#define GPAD 36
#define NITER (DV / GBK)   // 24

template<bool GATHER>
__global__ void __launch_bounds__(256)
gemm_kernel(const float* __restrict__ A, const float* __restrict__ W,
            const float* __restrict__ bias, float* __restrict__ C, int N,
            const int* __restrict__ idx) {
    __shared__ __align__(16) float As[2][GBM][GPAD];
    __shared__ __align__(16) float Ws[2][GBN][GPAD];
    int t = threadIdx.x;
    int tx = t & 15;                 // cols tx + 16j
    int ty = t >> 4;                 // rows ty*2 + i
    int bm = blockIdx.x * GBM, bn = blockIdx.y * GBN;

    int ar = t >> 3, ak = (t & 7) * 4;    // A tile: 1 float4/thread
    int wr = t >> 2, wk = (t & 3) * 8;    // W tile: 2 float4/thread

    const float *Arow0, *Arow1, *Arow2;
    bool u1 = false, u2 = false;
    if (GATHER) {
        int row = bm + ar;
        int bb = row / NPART, n = row - bb * NPART;
        int i0 = idx[(bb * TOPK + 0) * NPART + n];
        int i1 = idx[(bb * TOPK + 1) * NPART + n];
        int i2 = idx[(bb * TOPK + 2) * NPART + n];
        i0 = min(max(i0, 0), Pn - 1);
        i1 = min(max(i1, 0), Pn - 1);
        i2 = min(max(i2, 0), Pn - 1);
        u1 = (i1 != i0);
        u2 = (i2 != i0) && (i2 != i1);
        const float* base = A + (size_t)bb * Pn * DV;
        Arow0 = base + (size_t)i0 * DV;
        Arow1 = base + (size_t)i1 * DV;
        Arow2 = base + (size_t)i2 * DV;
    } else {
        Arow0 = A + (size_t)(bm + ar) * DV;
        Arow1 = Arow0; Arow2 = Arow0;
    }
    const float* Wg = W + (size_t)(bn + wr) * DV;

    auto loadA = [&](int k0) -> float4 {
        float4 s = *(const float4*)(Arow0 + k0 + ak);
        if (GATHER) {
            if (u1) { float4 v = *(const float4*)(Arow1 + k0 + ak);
                      s.x += v.x; s.y += v.y; s.z += v.z; s.w += v.w; }
            if (u2) { float4 v = *(const float4*)(Arow2 + k0 + ak);
                      s.x += v.x; s.y += v.y; s.z += v.z; s.w += v.w; }
        }
        return s;
    };

    unsigned long long acc2[2][4];
#pragma unroll
    for (int i = 0; i < 2; ++i)
#pragma unroll
        for (int j = 0; j < 4; ++j) acc2[i][j] = 0ull;

    // prologue: tile0 -> smem[0]; tile1 -> regs
    float4 a_r = loadA(0);
    float4 w_r0 = *(const float4*)(Wg + wk);
    float4 w_r1 = *(const float4*)(Wg + wk + 4);
    *(float4*)&As[0][ar][ak] = a_r;
    *(float4*)&Ws[0][wr][wk] = w_r0;
    *(float4*)&Ws[0][wr][wk + 4] = w_r1;
    a_r  = loadA(GBK);
    w_r0 = *(const float4*)(Wg + GBK + wk);
    w_r1 = *(const float4*)(Wg + GBK + wk + 4);
    __syncthreads();

#pragma unroll 1
    for (int i = 0; i < NITER; ++i) {
        int buf = i & 1, nbuf = buf ^ 1;
        if (i + 1 < NITER) {
            *(float4*)&As[nbuf][ar][ak] = a_r;
            *(float4*)&Ws[nbuf][wr][wk] = w_r0;
            *(float4*)&Ws[nbuf][wr][wk + 4] = w_r1;
        }
        if (i + 2 < NITER) {
            int k0 = (i + 2) * GBK;
            a_r  = loadA(k0);
            w_r0 = *(const float4*)(Wg + k0 + wk);
            w_r1 = *(const float4*)(Wg + k0 + wk + 4);
        }
#pragma unroll
        for (int kk = 0; kk < GBK; kk += 4) {
            ulonglong2 ap[2], wp[4];
            ap[0] = *(const ulonglong2*)&As[buf][ty * 2][kk];
            ap[1] = *(const ulonglong2*)&As[buf][ty * 2 + 1][kk];
#pragma unroll
            for (int j = 0; j < 4; ++j)
                wp[j] = *(const ulonglong2*)&Ws[buf][tx + 16 * j][kk];
#pragma unroll
            for (int ii = 0; ii < 2; ++ii)
#pragma unroll
                for (int j = 0; j < 4; ++j) {
                    fma2(acc2[ii][j], ap[ii].x, wp[j].x);
                    fma2(acc2[ii][j], ap[ii].y, wp[j].y);
                }
        }
        __syncthreads();
    }

#pragma unroll
    for (int i = 0; i < 2; ++i) {
        int row = bm + ty * 2 + i;
#pragma unroll
        for (int j = 0; j < 4; ++j) {
            int col = bn + tx + 16 * j;
            float x = pair_sum(acc2[i][j]) + bias[col];
            C[(size_t)row * N + col] = gelu_exact(x);
        }
    }
}

// ---------------------------------------------------------------------------
// logits: PER-WARP cp.async pipelines (no __syncthreads in main loop).
// Block = 128 threads; warp w owns rows {r0 + w*64 + l, +32} (RPT=2).
// Each warp stages its own 64-row x 8-k tiles (2KB) into its private
// 4-buffer ring. Per tile: wait_group(2) [own groups] -> __syncwarp()
// (~23cyc, no cross-warp straggler) -> issue tile+3 -> compute. Safe:
// lanes past syncwarp have issued their t-1 FMAs, so the LDS they depend
// on completed, making the buf (t-1)&3 overwrite race-free.
// R12/R14 showed block barriers convoy 16 warps/SM into lockstep: every
// pipe idled at ~35%. Decoupling warps removes barrier stalls and smooths
// the DRAM request stream.
// Store phase: 32 float4 spread 4x over all 8 bank-groups (minimal 4cyc);
// read phase: 32 consecutive float4 (conflict-free) via +4-row rotation.
// Dynamic smem: q 4 warps x 4 bufs x 2KB = 32KB + img 24KB = 56KB.
// ---------------------------------------------------------------------------
#define QT 8
#define NT (DT / QT)     // 64 tiles
#define RPT 2
#define TPB 128
#define RPB 256          // grid.x = ceil(9600/256) = 38 (last block guarded)
#define WROWS 64         // rows per warp
#define WBUF 128         // float4 per warp buffer (2 slots x 64 rows) = 2KB

__global__ void __launch_bounds__(TPB, 4)
logits_kernel(const float* __restrict__ q, float* __restrict__ out) {
    extern __shared__ __align__(16) float smem[];
    float4* q_s  = (float4*)smem;          // [4 warps][4 bufs][128] = 32KB
    float* img_s = smem + 8192;            // 12*512 floats = 24KB

    int t = threadIdx.x;
    int warp = t >> 5, lane = t & 31;
    int b = blockIdx.y;
    int r0 = blockIdx.x * RPB;

    const float* qB = q + (size_t)b * NQ * DT;

    // --- per-warp staging setup: 4 float4/lane/tile ---
    // idx = j*32 + lane -> row = idx>>1 (2 lanes per row, rows 0..63),
    // slot = idx&1. Persistent src pointers advanced +QT floats per tile.
    float4* wq = q_s + warp * (4 * WBUF);  // this warp's 4-buffer ring
    const float* srcp[4];
    unsigned dst0[4];                      // dst smem addr within buf 0
#pragma unroll
    for (int j = 0; j < 4; ++j) {
        int idx = j * 32 + lane;
        int row = idx >> 1, slot = idx & 1;
        int rg = r0 + warp * WROWS + row;
        if (rg > NQ - 1) rg = NQ - 1;      // last-block clamp
        srcp[j] = qB + (size_t)rg * DT + slot * 4;
        int rr = (row + 4 * slot) & (WROWS - 1);           // rotation: slot1 +4
        dst0[j] = (unsigned)__cvta_generic_to_shared(
            &wq[slot * WROWS + rr]);
    }

    auto issueTile = [&](int buf) {
        unsigned boff = (unsigned)buf * (WBUF * 16);       // bytes per buffer
#pragma unroll
        for (int j = 0; j < 4; ++j) {
            cp_async16(dst0[j] + boff, srcp[j]);
            srcp[j] += QT;
        }
        cp_commit();
    };

    // prologue: 3 groups in flight before first compute
    issueTile(0);
    issueTile(1);
    issueTile(2);

    {   // stage img tile for this batch (1536 float4, 12/thread)
        const float4* src = (const float4*)(g_img + (size_t)b * NPART * DT);
        float4* dst = (float4*)img_s;
#pragma unroll
        for (int i = 0; i < 12; ++i)
            dst[t + i * TPB] = src[t + i * TPB];
    }
    __syncthreads();

    // fused l2 normalization of the 12 img rows (4 warps, 3 rows each)
    for (int row = warp; row < NPART; row += 4) {
        float* rp = img_s + row * DT;
        float4 v0 = *(float4*)(rp + lane * 4);
        float4 v1 = *(float4*)(rp + lane * 4 + 128);
        float4 v2 = *(float4*)(rp + lane * 4 + 256);
        float4 v3 = *(float4*)(rp + lane * 4 + 384);
        float ss = v0.x*v0.x + v0.y*v0.y + v0.z*v0.z + v0.w*v0.w
                 + v1.x*v1.x + v1.y*v1.y + v1.z*v1.z + v1.w*v1.w
                 + v2.x*v2.x + v2.y*v2.y + v2.z*v2.z + v2.w*v2.w
                 + v3.x*v3.x + v3.y*v3.y + v3.z*v3.z + v3.w*v3.w;
#pragma unroll
        for (int off = 16; off > 0; off >>= 1)
            ss += __shfl_xor_sync(0xffffffffu, ss, off);
        float rinv = 1.0f / fmaxf(sqrtf(ss), 1e-12f);
        v0.x*=rinv; v0.y*=rinv; v0.z*=rinv; v0.w*=rinv;
        v1.x*=rinv; v1.y*=rinv; v1.z*=rinv; v1.w*=rinv;
        v2.x*=rinv; v2.y*=rinv; v2.z*=rinv; v2.w*=rinv;
        v3.x*=rinv; v3.y*=rinv; v3.z*=rinv; v3.w*=rinv;
        *(float4*)(rp + lane * 4)       = v0;
        *(float4*)(rp + lane * 4 + 128) = v1;
        *(float4*)(rp + lane * 4 + 256) = v2;
        *(float4*)(rp + lane * 4 + 384) = v3;
    }
    __syncthreads();   // img_s final for all warps; last block-wide barrier

    // hoisted, tile-invariant q LDS indices: [r][c] -> c*WROWS + rotated row
    int qidx[RPT][2];
#pragma unroll
    for (int r = 0; r < RPT; ++r)
#pragma unroll
        for (int c = 0; c < 2; ++c)
            qidx[r][c] = c * WROWS + ((lane + 32 * r + 4 * c) & (WROWS - 1));

    unsigned long long acc[RPT][13];
#pragma unroll
    for (int r = 0; r < RPT; ++r)
#pragma unroll
        for (int j = 0; j < 13; ++j) acc[r][j] = 0ull;

    int boff = 0;                          // float4 offset of current buffer
    const float* ik = img_s;               // advanced +QT floats per tile
#pragma unroll 1
    for (int tile = 0; tile < NT; ++tile) {
        // own pending groups at loop top = min(3, NT - tile)
        if (tile < NT - 2) cp_wait2();
        else if (tile == NT - 2) cp_wait1();
        else cp_wait0();
        __syncwarp();                // cross-lane visibility within the warp

        // issue tile+3 into buf (tile+3)&3 == (tile-1)&3: this warp's reads
        // of it completed (lanes past syncwarp => t-1 FMAs issued => LDS done)
        if (tile + 3 < NT) issueTile((tile + 3) & 3);

        const float4* qbuf = wq + boff;
#pragma unroll
        for (int c = 0; c < 2; ++c) {
            ulonglong2 qp[RPT];
#pragma unroll
            for (int r = 0; r < RPT; ++r)
                qp[r] = *(const ulonglong2*)&qbuf[qidx[r][c]];
#pragma unroll
            for (int n = 0; n < NPART; ++n) {
                ulonglong2 im = *(const ulonglong2*)&ik[n * DT + c * 4];
#pragma unroll
                for (int r = 0; r < RPT; ++r) {
                    fma2(acc[r][n], qp[r].x, im.x);
                    fma2(acc[r][n], qp[r].y, im.y);
                }
            }
#pragma unroll
            for (int r = 0; r < RPT; ++r) {
                fma2(acc[r][12], qp[r].x, qp[r].x);
                fma2(acc[r][12], qp[r].y, qp[r].y);
            }
        }
        ik += QT;
        boff += WBUF; if (boff == 4 * WBUF) boff = 0;
    }

#pragma unroll
    for (int r = 0; r < RPT; ++r) {
        int gr = r0 + warp * WROWS + lane + 32 * r;
        if (gr >= NQ) break;                  // last-block guard
        float s[13];
#pragma unroll
        for (int j = 0; j < 13; ++j) s[j] = pair_sum(acc[r][j]);
        float rinv = 1.0f / fmaxf(sqrtf(s[12]), 1e-12f);
#pragma unroll
        for (int n = 0; n < NPART; ++n)
            out[((size_t)(b * NPART + n)) * NQ + gr] = s[n] * rinv;
    }
}

// ---------------------------------------------------------------------------
// pred_logits[b,c] = sum_n logits[b,n,c*12+n]
// ---------------------------------------------------------------------------
__global__ void pred_kernel(float* __restrict__ out) {
    int t = blockIdx.x * blockDim.x + threadIdx.x;   // 0..25599
    if (t >= Bsz * NCLS) return;
    int b = t / NCLS, c = t % NCLS;
    float s = 0.0f;
#pragma unroll
    for (int n = 0; n < NPART; ++n)
        s += out[((size_t)(b * NPART + n)) * NQ + c * NPART + n];
    out[LOGITS_ELEMS + t] = s;
}

// ---------------------------------------------------------------------------
extern "C" void kernel_launch(void* const* d_in, const int* in_sizes, int n_in,
                              void* d_out, int out_size) {
    const float* image = (const float*)d_in[0];
    const float* query = (const float*)d_in[1];
    const int* topk = (const int*)d_in[2];
    const float* W1 = (const float*)d_in[3];
    const float* b1 = (const float*)d_in[4];
    const float* W2 = (const float*)d_in[5];
    const float* b2 = (const float*)d_in[6];
    const float* W3 = (const float*)d_in[7];
    const float* b3 = (const float*)d_in[8];
    float* out = (float*)d_out;

    float* h1; float* h2; float* img;
    cudaGetSymbolAddress((void**)&h1, g_h1);
    cudaGetSymbolAddress((void**)&h2, g_h2);
    cudaGetSymbolAddress((void**)&img, g_img);

    const int LOGITS_SMEM = 57344;   // 32KB q (4 warps x 4 bufs) + 24KB img
    cudaFuncSetAttribute(logits_kernel,
                         cudaFuncAttributeMaxDynamicSharedMemorySize,
                         LOGITS_SMEM);

    // launch order keeps logits at global index 5 (2 harness preamble
    // launches + 3 here) so ncu -s 5 -c 1 captures it.
    gemm_kernel<true ><<<dim3(MROWS / GBM, DV / GBN), 256>>>(image, W1, b1, h1, DV, topk);
    gemm_kernel<false><<<dim3(MROWS / GBM, DV / GBN), 256>>>(h1, W2, b2, h2, DV, nullptr);
    gemm_kernel<false><<<dim3(MROWS / GBM, DT / GBN), 256>>>(h2, W3, b3, img, DT, nullptr);
    logits_kernel<<<dim3((NQ + RPB - 1) / RPB, Bsz), TPB, LOGITS_SMEM>>>(query, out);
    pred_kernel<<<(Bsz * NCLS + 255) / 256, 256>>>(out);
}